// round 16
// baseline (speedup 1.0000x reference)
#include <cuda_runtime.h>
#include <cuda_bf16.h>
#include <cstdint>

typedef unsigned long long u64;

// Problem dims
#define TT 2048
#define BB 16
#define II 512
#define HH 512
#define BH (BB*HH)   // 8192
#define RR (TT/64)   // 32 scan rounds (64-step blocking)

#define CLUSTER 8    // CTAs per cluster = 1 batch per cluster, 64 cols per CTA

// Scratch: W^2..W^64, row-major [512][512]. Static __device__ (legal).
__device__ float g_W2[HH * HH];
__device__ float g_W4[HH * HH];
__device__ float g_W8[HH * HH];
__device__ float g_W16[HH * HH];
__device__ float g_W32[HH * HH];
__device__ float g_W64[HH * HH];

static __device__ __forceinline__ uint32_t smem_u32(const void* p) {
    uint32_t a;
    asm("{ .reg .u64 t; cvta.to.shared.u64 t, %1; cvt.u32.u64 %0, t; }"
        : "=r"(a) : "l"(p));
    return a;
}

#define FMA2(acc, a, b) \
    asm("fma.rn.f32x2 %0, %1, %2, %0;" : "+l"(acc) : "l"(a), "l"(b))
#define SPLAT2(dst, f) \
    asm("mov.b64 %0, {%1, %1};" : "=l"(dst) : "r"(__float_as_uint(f)))

// XOR swizzle: element (k, col) lives at physical column col ^ SWZ(k).
#define SWZ(kk) ((((kk) >> 2) & 7) << 2)

// ---------------------------------------------------------------------------
// Kernel 1: x_proj. 128x64 tile, 128 threads, 16-row x 4-col microtile
// (8 f32x2 m-pairs), swizzled smem (layout identical to proven R13/R14 tile).
// ---------------------------------------------------------------------------
__global__ __launch_bounds__(128)
void xproj_kernel(const float* __restrict__ A,      // inputs [M][512]
                  const float* __restrict__ W,      // weight [512][1024]
                  const float* __restrict__ bias,   // [512]
                  float* __restrict__ out)          // [M][512]
{
    __shared__ float As[32][132];
    __shared__ float Bs[32][68];

    const int tid = threadIdx.x;
    const int bm = blockIdx.x * 128;
    const int bn = blockIdx.y * 64;

    const int tx = tid & 15;    // col group: bn + tx*4
    const int ty = tid >> 4;    // row group: bm + ty*16 (0..7)

    u64 acc2[8][4];
#pragma unroll
    for (int r = 0; r < 8; r++)
#pragma unroll
        for (int c = 0; c < 4; c++) acc2[r][c] = 0ull;

#pragma unroll 1
    for (int kt = 0; kt < 16; kt++) {
        const int k0 = kt * 32;
        // A tile: 128 rows x 32 k = 1024 float4, 8 per thread
#pragma unroll
        for (int j = 0; j < 8; j++) {
            int idx = tid + j * 128;
            int row = idx >> 3;
            int q   = idx & 7;
            int sw  = (q << 2);
            float4 v = *reinterpret_cast<const float4*>(&A[(size_t)(bm + row) * 512 + k0 + q * 4]);
            As[q * 4 + 0][row ^ sw] = v.x;
            As[q * 4 + 1][row ^ sw] = v.y;
            As[q * 4 + 2][row ^ sw] = v.z;
            As[q * 4 + 3][row ^ sw] = v.w;
        }
        // B tile: 64 rows x 32 k = 512 float4, 4 per thread
#pragma unroll
        for (int j = 0; j < 4; j++) {
            int idx = tid + j * 128;
            int row = idx >> 3;
            int q   = idx & 7;
            int sw  = (q << 2);
            float4 v = *reinterpret_cast<const float4*>(&W[(size_t)(bn + row) * 1024 + 512 + k0 + q * 4]);
            Bs[q * 4 + 0][row ^ sw] = v.x;
            Bs[q * 4 + 1][row ^ sw] = v.y;
            Bs[q * 4 + 2][row ^ sw] = v.z;
            Bs[q * 4 + 3][row ^ sw] = v.w;
        }
        __syncthreads();

#pragma unroll
        for (int k = 0; k < 32; k++) {
            const int s4 = SWZ(k);
            ulonglong2 a0 = *reinterpret_cast<const ulonglong2*>(&As[k][(ty * 16     ) ^ s4]);
            ulonglong2 a1 = *reinterpret_cast<const ulonglong2*>(&As[k][(ty * 16 +  4) ^ s4]);
            ulonglong2 a2 = *reinterpret_cast<const ulonglong2*>(&As[k][(ty * 16 +  8) ^ s4]);
            ulonglong2 a3 = *reinterpret_cast<const ulonglong2*>(&As[k][(ty * 16 + 12) ^ s4]);
            float4 b = *reinterpret_cast<const float4*>(&Bs[k][(tx * 4) ^ s4]);
            u64 bs[4];
            SPLAT2(bs[0], b.x); SPLAT2(bs[1], b.y);
            SPLAT2(bs[2], b.z); SPLAT2(bs[3], b.w);
            u64 apair[8] = {a0.x, a0.y, a1.x, a1.y, a2.x, a2.y, a3.x, a3.y};
#pragma unroll
            for (int r = 0; r < 8; r++)
#pragma unroll
                for (int c = 0; c < 4; c++)
                    FMA2(acc2[r][c], apair[r], bs[c]);
        }
        __syncthreads();
    }

#pragma unroll
    for (int r = 0; r < 8; r++) {
        size_t row0 = (size_t)(bm + ty * 16 + 2 * r) * 512 + bn + tx * 4;
#pragma unroll
        for (int c = 0; c < 4; c++) {
            uint32_t lo, hi;
            asm("mov.b64 {%0, %1}, %2;" : "=r"(lo), "=r"(hi) : "l"(acc2[r][c]));
            float bv = bias[bn + tx * 4 + c];
            out[row0 + c]       = __uint_as_float(lo) + bv;
            out[row0 + 512 + c] = __uint_as_float(hi) + bv;
        }
    }
}

// ---------------------------------------------------------------------------
// Kernel 1b: matrix squaring: dst = src @ src (rows stride sstride).
// Proven body, runs on the forked branch (fully overlapped).
// ---------------------------------------------------------------------------
__global__ __launch_bounds__(256)
void mat_sq_kernel(const float* __restrict__ src, int sstride,
                   float* __restrict__ dst)
{
    __shared__ float As[32][68];   // [j][i]
    __shared__ float Bs[32][68];   // [j][k]

    const int tid = threadIdx.x;
    const int i0 = blockIdx.x * 64;
    const int k0g = blockIdx.y * 64;

    const int tx = tid & 15;
    const int ty = tid >> 4;

    float acc[4][4];
#pragma unroll
    for (int a = 0; a < 4; a++)
#pragma unroll
        for (int b = 0; b < 4; b++) acc[a][b] = 0.f;

#pragma unroll 1
    for (int jt = 0; jt < 16; jt++) {
        const int j0 = jt * 32;
#pragma unroll
        for (int l = 0; l < 2; l++) {
            int idx = tid + l * 256;
            int row = idx >> 3;
            int q   = idx & 7;
            float4 v = *reinterpret_cast<const float4*>(
                src + (size_t)(i0 + row) * sstride + j0 + q * 4);
            As[q * 4 + 0][row] = v.x;
            As[q * 4 + 1][row] = v.y;
            As[q * 4 + 2][row] = v.z;
            As[q * 4 + 3][row] = v.w;
        }
#pragma unroll
        for (int l = 0; l < 2; l++) {
            int idx = tid + l * 256;
            int jr  = idx >> 4;
            int q   = idx & 15;
            float4 v = *reinterpret_cast<const float4*>(
                src + (size_t)(j0 + jr) * sstride + k0g + q * 4);
            Bs[jr][q * 4 + 0] = v.x;
            Bs[jr][q * 4 + 1] = v.y;
            Bs[jr][q * 4 + 2] = v.z;
            Bs[jr][q * 4 + 3] = v.w;
        }
        __syncthreads();

#pragma unroll
        for (int j = 0; j < 32; j++) {
            float a[4], b[4];
#pragma unroll
            for (int x = 0; x < 4; x++) a[x] = As[j][ty * 4 + x];
#pragma unroll
            for (int x = 0; x < 4; x++) b[x] = Bs[j][tx * 4 + x];
#pragma unroll
            for (int x = 0; x < 4; x++)
#pragma unroll
                for (int y = 0; y < 4; y++)
                    acc[x][y] = fmaf(a[x], b[y], acc[x][y]);
        }
        __syncthreads();
    }

#pragma unroll
    for (int x = 0; x < 4; x++)
#pragma unroll
        for (int y = 0; y < 4; y++)
            dst[(size_t)(i0 + ty * 4 + x) * 512 + k0g + tx * 4 + y] = acc[x][y];
}

// ---------------------------------------------------------------------------
// Kernel 2: recurrent-side parallel GEMMs, swizzled 128x64 tile, 128 threads,
// 16-row x 4-col microtile. Row m -> (rr = m>>4, bb = m&15).
// Level s in {2,4,8,16,32,64}:
//  pre  (mode 0): A slot = s*rr + s/2-1 ; D slot = s*rr + s-1
//  post (mode 1): A = (rr==0 ? state : slot s*rr-1) ; D slot = s*rr + s/2-1
// ---------------------------------------------------------------------------
__global__ __launch_bounds__(128)
void rec_gemm_kernel(const float* __restrict__ Wp, int wstride,
                     const float* __restrict__ state,  // [16][512]
                     float* __restrict__ out,
                     int mode, int s)
{
    __shared__ float As[32][132];
    __shared__ float Bs[32][68];

    const int tid = threadIdx.x;
    const int bm = blockIdx.x * 128;
    const int bn = blockIdx.y * 64;

    const int tx = tid & 15;
    const int ty = tid >> 4;

    u64 acc2[8][4];
#pragma unroll
    for (int r = 0; r < 8; r++)
#pragma unroll
        for (int c = 0; c < 4; c++) acc2[r][c] = 0ull;

#pragma unroll 1
    for (int kt = 0; kt < 16; kt++) {
        const int k0 = kt * 32;
#pragma unroll
        for (int j = 0; j < 8; j++) {
            int idx = tid + j * 128;
            int row = idx >> 3;
            int q   = idx & 7;
            int sw  = (q << 2);
            int m   = bm + row;
            int rr  = m >> 4;
            int bb  = m & 15;
            const float* arow;
            if (mode == 0) {
                arow = out + (size_t)(s * rr + s / 2 - 1) * BH + (size_t)bb * 512;
            } else {
                arow = (rr == 0) ? (state + (size_t)bb * 512)
                                 : (out + (size_t)(s * rr - 1) * BH + (size_t)bb * 512);
            }
            float4 v = *reinterpret_cast<const float4*>(arow + k0 + q * 4);
            As[q * 4 + 0][row ^ sw] = v.x;
            As[q * 4 + 1][row ^ sw] = v.y;
            As[q * 4 + 2][row ^ sw] = v.z;
            As[q * 4 + 3][row ^ sw] = v.w;
        }
#pragma unroll
        for (int j = 0; j < 4; j++) {
            int idx = tid + j * 128;
            int row = idx >> 3;
            int q   = idx & 7;
            int sw  = (q << 2);
            float4 v = *reinterpret_cast<const float4*>(
                Wp + (size_t)(bn + row) * wstride + k0 + q * 4);
            Bs[q * 4 + 0][row ^ sw] = v.x;
            Bs[q * 4 + 1][row ^ sw] = v.y;
            Bs[q * 4 + 2][row ^ sw] = v.z;
            Bs[q * 4 + 3][row ^ sw] = v.w;
        }
        __syncthreads();

#pragma unroll
        for (int k = 0; k < 32; k++) {
            const int s4 = SWZ(k);
            ulonglong2 a0 = *reinterpret_cast<const ulonglong2*>(&As[k][(ty * 16     ) ^ s4]);
            ulonglong2 a1 = *reinterpret_cast<const ulonglong2*>(&As[k][(ty * 16 +  4) ^ s4]);
            ulonglong2 a2 = *reinterpret_cast<const ulonglong2*>(&As[k][(ty * 16 +  8) ^ s4]);
            ulonglong2 a3 = *reinterpret_cast<const ulonglong2*>(&As[k][(ty * 16 + 12) ^ s4]);
            float4 b = *reinterpret_cast<const float4*>(&Bs[k][(tx * 4) ^ s4]);
            u64 bs[4];
            SPLAT2(bs[0], b.x); SPLAT2(bs[1], b.y);
            SPLAT2(bs[2], b.z); SPLAT2(bs[3], b.w);
            u64 apair[8] = {a0.x, a0.y, a1.x, a1.y, a2.x, a2.y, a3.x, a3.y};
#pragma unroll
            for (int r = 0; r < 8; r++)
#pragma unroll
                for (int c = 0; c < 4; c++)
                    FMA2(acc2[r][c], apair[r], bs[c]);
        }
        __syncthreads();
    }

    // epilogue: C = acc + D, in place
#pragma unroll
    for (int r = 0; r < 8; r++) {
#pragma unroll
        for (int par = 0; par < 2; par++) {
            int m  = bm + ty * 16 + 2 * r + par;
            int rr = m >> 4;
            int bb = m & 15;
            size_t slot = (mode == 0) ? (size_t)(s * rr + s - 1)
                                      : (size_t)(s * rr + s / 2 - 1);
            float* crow = out + slot * BH + (size_t)bb * 512 + bn + tx * 4;
#pragma unroll
            for (int c = 0; c < 4; c++) {
                uint32_t lo, hi;
                asm("mov.b64 {%0, %1}, %2;" : "=r"(lo), "=r"(hi) : "l"(acc2[r][c]));
                float v = par ? __uint_as_float(hi) : __uint_as_float(lo);
                crow[c] = v + crow[c];
            }
        }
    }
}

// ---------------------------------------------------------------------------
// Kernel 3: cluster scan — proven protocol, 32 rounds with W64:
//   h_{64t+63} = W64 @ h_{64t-1} + c6_t ; c6_t in out[64t+63] (overwritten).
// ---------------------------------------------------------------------------
__global__ void __cluster_dims__(CLUSTER, 1, 1) __launch_bounds__(512, 1)
scan_kernel(const float* __restrict__ state,   // [16][512]
            float* __restrict__ out)           // [T][16][512] + last [16][512]
{
    __shared__ float hsh[2][512];              // double-buffered h
    __shared__ float red[8][65];               // k-split partials
    __shared__ __align__(8) u64 mbar[2];       // full[buf] barriers

    const int tid  = threadIdx.x;
    const int col  = tid & 63;
    const int ks   = tid >> 6;                 // k in [ks*64, ks*64+64)
    const int rank = blockIdx.x & (CLUSTER - 1);
    const int b    = blockIdx.x / CLUSTER;     // batch
    const int c0   = rank * 64;
    const int gcol = c0 + col;

    // ---- W64 slice into registers (f32x2-packed over k) ----
    u64 wreg[32];
    {
        const u64* wp = reinterpret_cast<const u64*>(
            g_W64 + (size_t)gcol * 512 + ks * 64);
#pragma unroll
        for (int j = 0; j < 32; j += 2) {
            ulonglong2 v = *reinterpret_cast<const ulonglong2*>(wp + j);
            wreg[j]     = v.x;
            wreg[j + 1] = v.y;
        }
    }

    // ---- init: h_{-1} = state, barriers, cluster-wide visibility ----
    hsh[0][tid] = state[(size_t)b * 512 + tid];
    const uint32_t bar0 = smem_u32(&mbar[0]);
    const uint32_t bar1 = smem_u32(&mbar[1]);
    if (tid == 0) {
        asm volatile("mbarrier.init.shared.b64 [%0], 1;" :: "r"(bar0) : "memory");
        asm volatile("mbarrier.init.shared.b64 [%0], 1;" :: "r"(bar1) : "memory");
    }
    __syncthreads();
    asm volatile("barrier.cluster.arrive.aligned;" ::: "memory");
    asm volatile("barrier.cluster.wait.aligned;" ::: "memory");

    // ---- prefetch c6_0 (slot 63) ----
    float xp = 0.f;
    if (tid < 64)
        xp = __ldcg(out + (size_t)63 * BH + (size_t)b * HH + c0 + tid);

    const uint32_t laddr_h0 = smem_u32(&hsh[0][gcol]);
    const uint32_t laddr_h1 = smem_u32(&hsh[1][gcol]);

#pragma unroll 1
    for (int t = 0; t < RR; t++) {
        const int rb = t & 1;
        const uint32_t barw = rb ? bar1 : bar0;

        // ---- 1. wait for h from all 8 CTAs (2048 tx bytes) ----
        if (t > 0) {
            if (tid == 0)
                asm volatile("mbarrier.arrive.expect_tx.shared.b64 _, [%0], 2048;"
                             :: "r"(barw) : "memory");
            const uint32_t parity = ((unsigned)(t - 1) >> 1) & 1u;
            uint32_t done;
            asm volatile(
                "{\n\t.reg .pred p;\n\t"
                "mbarrier.try_wait.parity.acquire.cta.shared::cta.b64 p, [%1], %2;\n\t"
                "selp.b32 %0, 1, 0, p;\n\t}"
                : "=r"(done) : "r"(barw), "r"(parity) : "memory");
            while (!done) {
                asm volatile(
                    "{\n\t.reg .pred p;\n\t"
                    "mbarrier.try_wait.parity.acquire.cta.shared::cta.b64 p, [%1], %2, 0x989680;\n\t"
                    "selp.b32 %0, 1, 0, p;\n\t}"
                    : "=r"(done) : "r"(barw), "r"(parity) : "memory");
            }
        }

        // ---- 2. compute: packed f32x2 dot over this thread's 64 k's ----
        u64 accp = 0ull;
        const u64* hp = reinterpret_cast<const u64*>(&hsh[rb][ks * 64]);
#pragma unroll
        for (int j = 0; j < 32; j += 2) {
            ulonglong2 h2 = *reinterpret_cast<const ulonglong2*>(hp + j);
            FMA2(accp, wreg[j],     h2.x);
            FMA2(accp, wreg[j + 1], h2.y);
        }
        {
            uint32_t lo, hi;
            asm("mov.b64 {%0, %1}, %2;" : "=r"(lo), "=r"(hi) : "l"(accp));
            red[ks][col] = __uint_as_float(lo) + __uint_as_float(hi);
        }
        __syncthreads();

        // ---- 3. finalize (tid<64): reduce, publish via st.async, store out ----
        if (tid < 64) {
            float s = 0.f;
#pragma unroll
            for (int r = 0; r < 8; r++) s += red[r][tid];
            const float hn = s + xp;

            if (t + 1 < RR) {
                const uint32_t ldst = rb ? laddr_h0 : laddr_h1;
                const uint32_t lbar = rb ? bar0 : bar1;
#pragma unroll
                for (int r = 0; r < CLUSTER; r++) {
                    uint32_t raddr, rbar;
                    asm volatile("mapa.shared::cluster.u32 %0, %1, %2;"
                                 : "=r"(raddr) : "r"(ldst), "r"(r));
                    asm volatile("mapa.shared::cluster.u32 %0, %1, %2;"
                                 : "=r"(rbar) : "r"(lbar), "r"(r));
                    asm volatile(
                        "st.async.weak.shared::cluster.mbarrier::complete_tx::bytes.f32 [%0], %1, [%2];"
                        :: "r"(raddr), "f"(hn), "r"(rbar) : "memory");
                }
            }

            // out[64t+63] = h_{64t+63}
            const size_t off = (size_t)(64 * t + 63) * BH + (size_t)b * HH + c0 + tid;
            __stcg(out + off, hn);
            if (t == RR - 1)
                __stcg(out + (size_t)TT * BH + (size_t)b * HH + c0 + tid, hn);
            // prefetch c6_{t+1} from out[64t+127]
            if (t + 1 < RR)
                xp = __ldcg(out + (size_t)(64 * t + 127) * BH + (size_t)b * HH + c0 + tid);
        }
    }

    // ---- drain ----
    asm volatile("barrier.cluster.arrive.aligned;" ::: "memory");
    asm volatile("barrier.cluster.wait.aligned;" ::: "memory");
}

// ---------------------------------------------------------------------------
// Launch. Graph topology:
//   branch A (default stream): xproj -> pre(2) -> [join] -> pre(4..64) ->
//                              scan -> post(64..2)
//   branch B (forked stream):  W2 -> W4 -> W8 -> W16 -> W32 -> W64
// Fork/join via disable-timing events (host objects only; leaked — replays
// execute the captured graph, not this function).
// ---------------------------------------------------------------------------
extern "C" void kernel_launch(void* const* d_in, const int* in_sizes, int n_in,
                              void* d_out, int out_size) {
    const float* inputs = (const float*)d_in[0];  // [T][B][I]
    const float* state  = (const float*)d_in[1];  // [B][H]
    const float* weight = (const float*)d_in[2];  // [H][I+H]
    const float* bias   = (const float*)d_in[3];  // [H]
    float* out = (float*)d_out;                   // [T][B][H] outputs, then [B][H] last

    float *W2, *W4, *W8, *W16, *W32, *W64;
    cudaGetSymbolAddress((void**)&W2,  g_W2);
    cudaGetSymbolAddress((void**)&W4,  g_W4);
    cudaGetSymbolAddress((void**)&W8,  g_W8);
    cudaGetSymbolAddress((void**)&W16, g_W16);
    cudaGetSymbolAddress((void**)&W32, g_W32);
    cudaGetSymbolAddress((void**)&W64, g_W64);

    cudaStream_t s2;
    cudaStreamCreateWithFlags(&s2, cudaStreamNonBlocking);
    cudaEvent_t e1, e2;
    cudaEventCreateWithFlags(&e1, cudaEventDisableTiming);
    cudaEventCreateWithFlags(&e2, cudaEventDisableTiming);

    dim3 gw(8, 8);     // 512/64 x 512/64

    // ---- fork: W-power chain on branch B ----
    cudaEventRecord(e1, 0);
    cudaStreamWaitEvent(s2, e1, 0);
    mat_sq_kernel<<<gw, 256, 0, s2>>>(weight, 1024, W2);   // W2  = Whh^2
    mat_sq_kernel<<<gw, 256, 0, s2>>>(W2,  512, W4);
    mat_sq_kernel<<<gw, 256, 0, s2>>>(W4,  512, W8);
    mat_sq_kernel<<<gw, 256, 0, s2>>>(W8,  512, W16);
    mat_sq_kernel<<<gw, 256, 0, s2>>>(W16, 512, W32);
    mat_sq_kernel<<<gw, 256, 0, s2>>>(W32, 512, W64);
    cudaEventRecord(e2, s2);

    // ---- branch A: xproj + pre s=2 (need only weight/inputs) ----
    dim3 g1(256, 8);   // M=32768 / 128, N=512 / 64
    xproj_kernel<<<g1, 128>>>(inputs, weight, bias, out);

    dim3 g16k(128, 8); // M=16384 / 128
    dim3 g8k(64, 8);   // M=8192 / 128
    dim3 g4k(32, 8);   // M=4096 / 128
    dim3 g2k(16, 8);   // M=2048 / 128
    dim3 g1k(8, 8);    // M=1024 / 128
    dim3 g512(4, 8);   // M=512  / 128

    rec_gemm_kernel<<<g16k, 128>>>(weight, 1024, state, out, 0, 2);   // pre s=2

    // ---- join: everything below needs W-powers ----
    cudaStreamWaitEvent(0, e2, 0);

    rec_gemm_kernel<<<g8k,  128>>>(W2,  512, state, out, 0, 4);       // pre s=4
    rec_gemm_kernel<<<g4k,  128>>>(W4,  512, state, out, 0, 8);       // pre s=8
    rec_gemm_kernel<<<g2k,  128>>>(W8,  512, state, out, 0, 16);      // pre s=16
    rec_gemm_kernel<<<g1k,  128>>>(W16, 512, state, out, 0, 32);      // pre s=32
    rec_gemm_kernel<<<g512, 128>>>(W32, 512, state, out, 0, 64);      // pre s=64

    scan_kernel<<<BB * CLUSTER, 512>>>(state, out);                   // 32 rounds, W64

    rec_gemm_kernel<<<g512, 128>>>(W32, 512, state, out, 1, 64);      // post s=64
    rec_gemm_kernel<<<g1k,  128>>>(W16, 512, state, out, 1, 32);      // post s=32
    rec_gemm_kernel<<<g2k,  128>>>(W8,  512, state, out, 1, 16);      // post s=16
    rec_gemm_kernel<<<g4k,  128>>>(W4,  512, state, out, 1, 8);       // post s=8
    rec_gemm_kernel<<<g8k,  128>>>(W2,  512, state, out, 1, 4);       // post s=4
    rec_gemm_kernel<<<g16k, 128>>>(weight, 1024, state, out, 1, 2);   // post s=2

    (void)in_sizes; (void)n_in; (void)out_size;
}